// round 4
// baseline (speedup 1.0000x reference)
#include <cuda_runtime.h>
#include <cuda_bf16.h>

// YOLOv3 loss, sm_103a — single fused kernel, R4.
// Back to APT=1 (R3 showed warp count > per-thread ILP for this latency-bound
// loop). Division-free IoU argmax kept; loop-carried select chain split into
// independent even/odd chains merged at the end.

#define NUM_CLASSES 80
#define MAXB 64
#define MAXM 64
#define TPB 256
#define IOU_THRESH 0.5f

__device__ float        g_cls_sum[MAXB];   // zero-initialized at module load
__device__ float        g_reg_sum[MAXB];
__device__ float        g_npos[MAXB];
__device__ unsigned int g_done;

__device__ __forceinline__ float sigmoidf_fast(float x) {
    return 1.0f / (1.0f + __expf(-x));
}

__global__ void __launch_bounds__(TPB)
yolo_loss_fused(const float* __restrict__ pred,
                const float* __restrict__ ann,
                const float* __restrict__ anchors,
                float* __restrict__ out,
                int A, int M, int B) {
    __shared__ float4 s_corners[MAXM];               // x1,y1,x2,y2
    __shared__ float  s_area[MAXM];
    __shared__ float  s_cx[MAXM], s_cy[MAXM], s_w[MAXM], s_h[MAXM], s_cl[MAXM];
    __shared__ int    s_cnt;
    __shared__ int    s_last;

    const int b   = blockIdx.y;
    const int tid = threadIdx.x;

    // ---- warp 0: load + compact valid boxes (M <= 32), order-preserving ----
    if (tid < 32) {
        bool  valid = false;
        float x = 0.f, y = 0.f, w = 0.f, h = 0.f, cl = -1.f;
        if (tid < M) {
            const float* bm = ann + ((size_t)b * M + tid) * 5;
            x = bm[0]; y = bm[1]; w = bm[2]; h = bm[3]; cl = bm[4];
            valid = (cl != -1.0f);
        }
        unsigned mask = __ballot_sync(0xffffffffu, valid);
        if (valid) {
            int slot = __popc(mask & ((1u << tid) - 1u));
            s_corners[slot] = make_float4(x, y, x + w, y + h);
            s_area[slot] = w * h;
            s_cx[slot] = x + 0.5f * w;
            s_cy[slot] = y + 0.5f * h;
            s_w[slot]  = w;
            s_h[slot]  = h;
            s_cl[slot] = cl;
        }
        if (tid == 0) s_cnt = __popc(mask);
    }
    __syncthreads();

    const int cnt = s_cnt;
    const int a   = blockIdx.x * TPB + tid;
    float clsc = 0.f, regc = 0.f, posc = 0.f;

    if (a < A) {
        const float4 an = __ldg((const float4*)anchors + a);
        const float ax = an.x, ay = an.y, aw = an.z, ah = an.w;
        const float ax1 = ax - 0.5f * aw, ay1 = ay - 0.5f * ah;
        const float ax2 = ax + 0.5f * aw, ay2 = ay + 0.5f * ah;
        const float areaA = aw * ah;

        // Best tracked as (inter, union); a/b > c/d  ⟺  a*d > c*b (unions>0).
        // Two independent chains (even m / odd m) halve the serial dep chain.
        // Init (-1,1): any real candidate beats it; strict '>' keeps first max.
        float I0 = -1.f, U0 = 1.f;  int i0 = 0;
        float I1 = -1.f, U1 = 1.f;  int i1 = 1;

        int m = 0;
        #pragma unroll 4
        for (; m + 1 < cnt; m += 2) {
            const float4 c0 = s_corners[m];
            const float4 c1 = s_corners[m + 1];
            float iw0 = fmaxf(fminf(ax2, c0.z) - fmaxf(ax1, c0.x), 0.f);
            float ih0 = fmaxf(fminf(ay2, c0.w) - fmaxf(ay1, c0.y), 0.f);
            float iw1 = fmaxf(fminf(ax2, c1.z) - fmaxf(ax1, c1.x), 0.f);
            float ih1 = fmaxf(fminf(ay2, c1.w) - fmaxf(ay1, c1.y), 0.f);
            float in0 = iw0 * ih0;
            float in1 = iw1 * ih1;
            float un0 = areaA + s_area[m]     - in0;
            float un1 = areaA + s_area[m + 1] - in1;
            if (in0 * U0 > I0 * un0) { I0 = in0; U0 = un0; i0 = m; }
            if (in1 * U1 > I1 * un1) { I1 = in1; U1 = un1; i1 = m + 1; }
        }
        if (m < cnt) {  // odd tail
            const float4 c0 = s_corners[m];
            float iw0 = fmaxf(fminf(ax2, c0.z) - fmaxf(ax1, c0.x), 0.f);
            float ih0 = fmaxf(fminf(ay2, c0.w) - fmaxf(ay1, c0.y), 0.f);
            float in0 = iw0 * ih0;
            float un0 = areaA + s_area[m] - in0;
            if (in0 * U0 > I0 * un0) { I0 = in0; U0 = un0; i0 = m; }
        }

        // merge chains: odd wins only on strictly greater IoU (exact nonzero
        // ties across chains are measure-zero on continuous inputs; all-zero
        // anchors are negatives where bi is never consumed)
        float bI = I0, bU = U0;  int bi = i0;
        if (I1 * U0 > I0 * U1) { bI = I1; bU = U1; bi = i1; }

        // best_iou >= 0.5  ⟺  2*best_inter >= best_union
        if (2.0f * bI >= bU) {
            posc = 1.f;
            const float* row = pred + ((size_t)b * A + a) * (NUM_CLASSES + 5);

            // regression: sum of squared errors (both /denom deferred)
            float r0 = row[0], r1 = row[1], r2 = row[2], r3 = row[3], r4 = row[4];
            float stx = sigmoidf_fast(s_cx[bi] - ax);
            float sty = sigmoidf_fast(s_cy[bi] - ay);
            float tw  = __logf(fmaxf(s_w[bi], 1.f) / aw);
            float th  = __logf(fmaxf(s_h[bi], 1.f) / ah);
            float d0 = sigmoidf_fast(r0) - stx;
            float d1 = sigmoidf_fast(r1) - sty;
            float d2 = r2 - tw;
            float d3 = r3 - th;
            float d4 = r4 - 1.0f;
            regc = d0*d0 + d1*d1 + d2*d2 + d3*d3 + d4*d4;

            // one-hot BCE collapsed: -( log p_t - log(1-p_t) + sum_c log(1-p_c) )
            float acc = 0.f;
            #pragma unroll 8
            for (int c = 0; c < NUM_CLASSES; c++)
                acc += __logf(1.0f - row[5 + c]);
            int t = (int)s_cl[bi];
            float pt = row[5 + t];
            clsc = -(__logf(pt) - __logf(1.0f - pt) + acc);
        }
    }

    // warp reduce, one conditional atomic triple per warp
    const unsigned full = 0xffffffffu;
    #pragma unroll
    for (int off = 16; off > 0; off >>= 1) {
        clsc += __shfl_down_sync(full, clsc, off);
        regc += __shfl_down_sync(full, regc, off);
        posc += __shfl_down_sync(full, posc, off);
    }
    if ((tid & 31) == 0 && posc > 0.f) {
        atomicAdd(&g_cls_sum[b], clsc);
        atomicAdd(&g_reg_sum[b], regc);
        atomicAdd(&g_npos[b],    posc);
    }

    // ---- last-block finalize ----
    __syncthreads();
    if (tid == 0) {
        __threadfence();
        unsigned total = gridDim.x * gridDim.y;
        unsigned old = atomicAdd(&g_done, 1u);
        s_last = (old == total - 1u);
    }
    __syncthreads();

    if (s_last && tid < 32) {
        __threadfence();
        float cl = 0.f, rg = 0.f;
        if (tid < B) {
            float n = g_npos[tid];
            float denom = fmaxf(n, 1.f);
            cl = g_cls_sum[tid] / denom;
            rg = (n > 0.f) ? g_reg_sum[tid] / (denom * denom) : 0.f;
            g_cls_sum[tid] = 0.f;
            g_reg_sum[tid] = 0.f;
            g_npos[tid]    = 0.f;
        }
        #pragma unroll
        for (int off = 16; off > 0; off >>= 1) {
            cl += __shfl_down_sync(full, cl, off);
            rg += __shfl_down_sync(full, rg, off);
        }
        if (tid == 0) {
            out[0] = cl / (float)B;
            out[1] = rg / (float)B;
            g_done = 0u;
        }
    }
}

extern "C" void kernel_launch(void* const* d_in, const int* in_sizes, int n_in,
                              void* d_out, int out_size) {
    const float* pred    = (const float*)d_in[0];  // (B, A, 5+C) f32
    const float* ann     = (const float*)d_in[1];  // (B, M, 5) f32
    const float* anchors = (const float*)d_in[2];  // (A, 4) f32
    float* out = (float*)d_out;

    const int A = in_sizes[2] / 4;
    const int B = in_sizes[0] / (A * (NUM_CLASSES + 5));
    const int M = in_sizes[1] / (B * 5);

    dim3 grid((A + TPB - 1) / TPB, B);
    yolo_loss_fused<<<grid, TPB>>>(pred, ann, anchors, out, A, M, B);
}

// round 5
// speedup vs baseline: 1.0601x; 1.0601x over previous
#include <cuda_runtime.h>
#include <cuda_bf16.h>

// YOLOv3 loss, sm_103a — single fused kernel, R5.
// R5: __launch_bounds__(256,8) caps regs at 32 -> 64/64 warps/SM theoretical
// (R2/R4 were stuck at 52% occ with regs=40). Box list padded to a fixed 32
// with inert dummies -> compile-time trip count, full unroll, batched LDS.

#define NUM_CLASSES 80
#define MAXB 64
#define MLOOP 32          // fixed trip count (M = 32 for this problem)
#define TPB 256

__device__ float        g_cls_sum[MAXB];   // zero-initialized at module load
__device__ float        g_reg_sum[MAXB];
__device__ float        g_npos[MAXB];
__device__ unsigned int g_done;

__device__ __forceinline__ float sigmoidf_fast(float x) {
    return 1.0f / (1.0f + __expf(-x));
}

__global__ void __launch_bounds__(TPB, 8)
yolo_loss_fused(const float* __restrict__ pred,
                const float* __restrict__ ann,
                const float* __restrict__ anchors,
                float* __restrict__ out,
                int A, int M, int B) {
    __shared__ float4 s_corners[MLOOP];              // x1,y1,x2,y2
    __shared__ float  s_area[MLOOP];
    __shared__ float  s_cx[MLOOP], s_cy[MLOOP], s_w[MLOOP], s_h[MLOOP], s_cl[MLOOP];
    __shared__ int    s_last;

    const int b   = blockIdx.y;
    const int tid = threadIdx.x;

    // ---- warp 0: compact valid boxes (order-preserving), pad with dummies ----
    // Dummy: inverted corners -> intersection always 0; union = areaA + 1 > 0.
    // A dummy can transiently win the argmax only when every real IoU is 0,
    // in which case the anchor is negative (2*0 >= U is false) and bi is
    // never consumed. cnt==0 (no valid boxes) likewise yields zero losses,
    // matching the reference's has_valid gating.
    if (tid < 32) {
        // phase 1: every lane writes a dummy to its own slot
        s_corners[tid] = make_float4(1e30f, 1e30f, -1e30f, -1e30f);
        s_area[tid] = 1.f;
        s_cx[tid] = 0.f; s_cy[tid] = 0.f; s_w[tid] = 1.f; s_h[tid] = 1.f;
        s_cl[tid] = 0.f;
        __syncwarp();
        // phase 2: valid lanes overwrite compacted slots
        bool  valid = false;
        float x = 0.f, y = 0.f, w = 0.f, h = 0.f, cl = -1.f;
        if (tid < M) {
            const float* bm = ann + ((size_t)b * M + tid) * 5;
            x = bm[0]; y = bm[1]; w = bm[2]; h = bm[3]; cl = bm[4];
            valid = (cl != -1.0f);
        }
        unsigned mask = __ballot_sync(0xffffffffu, valid);
        if (valid) {
            int slot = __popc(mask & ((1u << tid) - 1u));
            s_corners[slot] = make_float4(x, y, x + w, y + h);
            s_area[slot] = w * h;
            s_cx[slot] = x + 0.5f * w;
            s_cy[slot] = y + 0.5f * h;
            s_w[slot]  = w;
            s_h[slot]  = h;
            s_cl[slot] = cl;
        }
    }
    __syncthreads();

    const int a = blockIdx.x * TPB + tid;
    float clsc = 0.f, regc = 0.f, posc = 0.f;

    if (a < A) {
        const float4 an = __ldg((const float4*)anchors + a);
        const float ax = an.x, ay = an.y, aw = an.z, ah = an.w;
        const float ax1 = ax - 0.5f * aw, ay1 = ay - 0.5f * ah;
        const float ax2 = ax + 0.5f * aw, ay2 = ay + 0.5f * ah;
        const float areaA = aw * ah;

        // Best as (inter, union); a/b > c/d  ⟺  a*d > c*b  (unions > 0).
        // Init (-1,1): first candidate wins; strict '>' keeps the first max
        // afterwards -> matches jnp.argmax over the compacted order.
        float bI = -1.f, bU = 1.f;
        int   bi = 0;

        #pragma unroll
        for (int m = 0; m < MLOOP; m++) {
            const float4 c = s_corners[m];
            float iw = fmaxf(fminf(ax2, c.z) - fmaxf(ax1, c.x), 0.f);
            float ih = fmaxf(fminf(ay2, c.w) - fmaxf(ay1, c.y), 0.f);
            float inter = iw * ih;
            float uni   = areaA + s_area[m] - inter;
            if (inter * bU > bI * uni) { bI = inter; bU = uni; bi = m; }
        }

        // best_iou >= 0.5  ⟺  2*best_inter >= best_union
        if (2.0f * bI >= bU) {
            posc = 1.f;
            const float* row = pred + ((size_t)b * A + a) * (NUM_CLASSES + 5);

            // regression: sum of squared errors (both /denom deferred)
            float r0 = row[0], r1 = row[1], r2 = row[2], r3 = row[3], r4 = row[4];
            float stx = sigmoidf_fast(s_cx[bi] - ax);
            float sty = sigmoidf_fast(s_cy[bi] - ay);
            float tw  = __logf(fmaxf(s_w[bi], 1.f) / aw);
            float th  = __logf(fmaxf(s_h[bi], 1.f) / ah);
            float d0 = sigmoidf_fast(r0) - stx;
            float d1 = sigmoidf_fast(r1) - sty;
            float d2 = r2 - tw;
            float d3 = r3 - th;
            float d4 = r4 - 1.0f;
            regc = d0*d0 + d1*d1 + d2*d2 + d3*d3 + d4*d4;

            // one-hot BCE collapsed: -( log p_t - log(1-p_t) + sum_c log(1-p_c) )
            float acc = 0.f;
            #pragma unroll 8
            for (int c = 0; c < NUM_CLASSES; c++)
                acc += __logf(1.0f - row[5 + c]);
            int t = (int)s_cl[bi];
            float pt = row[5 + t];
            clsc = -(__logf(pt) - __logf(1.0f - pt) + acc);
        }
    }

    // warp reduce, one conditional atomic triple per warp
    const unsigned full = 0xffffffffu;
    #pragma unroll
    for (int off = 16; off > 0; off >>= 1) {
        clsc += __shfl_down_sync(full, clsc, off);
        regc += __shfl_down_sync(full, regc, off);
        posc += __shfl_down_sync(full, posc, off);
    }
    if ((tid & 31) == 0 && posc > 0.f) {
        atomicAdd(&g_cls_sum[b], clsc);
        atomicAdd(&g_reg_sum[b], regc);
        atomicAdd(&g_npos[b],    posc);
    }

    // ---- last-block finalize ----
    __syncthreads();
    if (tid == 0) {
        __threadfence();
        unsigned total = gridDim.x * gridDim.y;
        unsigned old = atomicAdd(&g_done, 1u);
        s_last = (old == total - 1u);
    }
    __syncthreads();

    if (s_last && tid < 32) {
        __threadfence();
        float cl = 0.f, rg = 0.f;
        if (tid < B) {
            float n = g_npos[tid];
            float denom = fmaxf(n, 1.f);
            cl = g_cls_sum[tid] / denom;
            rg = (n > 0.f) ? g_reg_sum[tid] / (denom * denom) : 0.f;
            g_cls_sum[tid] = 0.f;
            g_reg_sum[tid] = 0.f;
            g_npos[tid]    = 0.f;
        }
        #pragma unroll
        for (int off = 16; off > 0; off >>= 1) {
            cl += __shfl_down_sync(full, cl, off);
            rg += __shfl_down_sync(full, rg, off);
        }
        if (tid == 0) {
            out[0] = cl / (float)B;
            out[1] = rg / (float)B;
            g_done = 0u;
        }
    }
}

extern "C" void kernel_launch(void* const* d_in, const int* in_sizes, int n_in,
                              void* d_out, int out_size) {
    const float* pred    = (const float*)d_in[0];  // (B, A, 5+C) f32
    const float* ann     = (const float*)d_in[1];  // (B, M, 5) f32
    const float* anchors = (const float*)d_in[2];  // (A, 4) f32
    float* out = (float*)d_out;

    const int A = in_sizes[2] / 4;
    const int B = in_sizes[0] / (A * (NUM_CLASSES + 5));
    const int M = in_sizes[1] / (B * 5);

    dim3 grid((A + TPB - 1) / TPB, B);
    yolo_loss_fused<<<grid, TPB>>>(pred, ann, anchors, out, A, M, B);
}